// round 12
// baseline (speedup 1.0000x reference)
#include <cuda_runtime.h>
#include <cstdint>

#define NPTS   60000
#define KOFF   27
#define CIN    2
#define COUT   64
#define BB     2
#define DD     12
#define HH     200
#define WW     200
#define CELLS  960000        // 2*12*200*200
#define EPS_LN 1e-5f

#define ROWS_TOTAL (BB * DD * HH)        // 4800 blocks
#define WARPS_PER_BLOCK 8
#define CELLS_PER_WARP  (WW / WARPS_PER_BLOCK)   // 25
#define CHUNK 5                                   // cells processed per phase

#define GROW 202                                  // padded row: [-1 | 200 | -1]
#define EMPTY16 0xFFFFu

// Dense cell -> point-id lookup grid (3.84 MB, L2-resident). -1 = empty.
__device__ int g_pointgrid[CELLS];
// Channel-mean weight vectors: wbar[j] = (1/64) sum_q w_jq  (2-vec).
__device__ float2 g_wbar[KOFF];

// --------------------------------------------------------------------------
// Kernel 1: init point grid to -1.
// --------------------------------------------------------------------------
__global__ void init_grid_kernel() {
    int i = blockIdx.x * blockDim.x + threadIdx.x;
    if (i < CELLS / 4)
        reinterpret_cast<int4*>(g_pointgrid)[i] = make_int4(-1, -1, -1, -1);
}

// --------------------------------------------------------------------------
// Kernel 2: fill point grid. scat[13*NPTS + n] is point n's own cell index.
// --------------------------------------------------------------------------
__global__ void fill_grid_kernel(const int* __restrict__ scat) {
    int n = blockIdx.x * blockDim.x + threadIdx.x;
    if (n < NPTS)
        g_pointgrid[scat[13 * NPTS + n]] = n;
}

// --------------------------------------------------------------------------
// Kernel 2b: precompute wbar (27 threads, trivial).
// --------------------------------------------------------------------------
__global__ void wbar_kernel(const float* __restrict__ weight) {  // [27,2,64]
    int t = threadIdx.x;
    if (t < KOFF) {
        float s0 = 0.f, s1 = 0.f;
        #pragma unroll 8
        for (int q = 0; q < COUT; q++) {
            s0 += weight[(t * 2 + 0) * COUT + q];
            s1 += weight[(t * 2 + 1) * COUT + q];
        }
        g_wbar[t] = make_float2(s0 * (1.f / COUT), s1 * (1.f / COUT));
    }
}

// --------------------------------------------------------------------------
// Kernel 3: fused gather-conv + LayerNorm + ReLU (R8 layout).
// One block per (b, z, y) row; warp per cell (5-cell chunks). Lane i owns
// channels {2i, 2i+1}. act[ci] is WARP-UNIFORM, so inactive cells branch
// around the hit loop / butterfly / epilogue with zero divergence.
// --------------------------------------------------------------------------
__global__ __launch_bounds__(256, 7) void fused_kernel(
        const float2* __restrict__ feat,     // [NPTS] as float2
        const float2* __restrict__ weight2,  // float2 view of [27,2,64]
        const float*  __restrict__ gamma,
        const float*  __restrict__ beta,
        float* __restrict__ out) {           // [CELLS, 64]
    __shared__ float4 swpx[KOFF][33];                          // 14256 B
    __shared__ unsigned short sgrid[9 * GROW];                 //  3636 B
    __shared__ float2 sfeat[WARPS_PER_BLOCK][CHUNK][32];       // 10240 B

    // decode row
    const int row = blockIdx.x;          // (b*DD + z)*HH + y
    const int y   = row % HH;
    const int bz  = row / HH;            // b*DD + z
    const int z   = bz % DD;
    const int rowbase = row * WW;        // linear cell index of x=0

    // ---- stage packed weights: swpx[j][lane] = (w0.x, w0.y, w1.x, w1.y) ----
    for (int i = threadIdx.x; i < KOFF * 32; i += blockDim.x) {
        const int j = i >> 5, ln = i & 31;
        const float2 w0 = weight2[(j * 2 + 0) * (COUT / 2) + ln];
        const float2 w1 = weight2[(j * 2 + 1) * (COUT / 2) + ln];
        swpx[j][ln] = make_float4(w0.x, w0.y, w1.x, w1.y);
    }
    if (threadIdx.x < KOFF) {
        const float2 wb = g_wbar[threadIdx.x];
        swpx[threadIdx.x][32] = make_float4(wb.x, wb.y, 0.f, 0.f);
    }

    // ---- stage 9 neighbor grid rows with halo (uint16, 0xFFFF = empty) ----
    for (int i = threadIdx.x; i < 9 * GROW; i += blockDim.x) {
        const int r  = i / GROW;         // 0..8 -> (dz+1)*3 + (dy+1)
        const int c  = i - r * GROW;     // 0..201 -> x = c-1
        const int dz = r / 3 - 1;
        const int dy = r % 3 - 1;
        const int nz = z + dz, ny = y + dy, nx = c - 1;
        int v = -1;
        if ((unsigned)nz < DD && (unsigned)ny < HH && (unsigned)nx < WW)
            v = g_pointgrid[rowbase + (dz * HH + dy) * WW + nx];
        sgrid[i] = (v < 0) ? (unsigned short)EMPTY16 : (unsigned short)v;
    }
    __syncthreads();

    const int lane = threadIdx.x & 31;
    const int wib  = threadIdx.x >> 5;

    const float2 gg = reinterpret_cast<const float2*>(gamma)[lane];
    const float2 bb = reinterpret_cast<const float2*>(beta)[lane];

    // lane -> (k, smem probe base)
    const int dxl   = lane % 3;                         // dx+1 for lanes<27
    const int srow  = (lane < KOFF) ? (lane / 3) : 0;   // (dz+1)*3+(dy+1)
    const int pbase = srow * GROW + dxl;                // + x gives probe index
    const bool probing = (lane < KOFF);

    const int x0 = wib * CELLS_PER_WARP;

    for (int c0 = 0; c0 < CELLS_PER_WARP; c0 += CHUNK) {
        // ---- phase 1: probes (LDS.U16) ----
        unsigned pt[CHUNK];
        #pragma unroll
        for (int ci = 0; ci < CHUNK; ci++) {
            const int x = x0 + c0 + ci;
            pt[ci] = probing ? (unsigned)sgrid[pbase + x] : EMPTY16;
        }

        // ---- phase 2: ballots; per-cell zero store for inactive ----
        unsigned act[CHUNK];
        #pragma unroll
        for (int ci = 0; ci < CHUNK; ci++)
            act[ci] = __ballot_sync(0xffffffffu, pt[ci] != EMPTY16);

        const int cellbase = rowbase + x0 + c0;
        #pragma unroll
        for (int ci = 0; ci < CHUNK; ci++) {
            if (act[ci] == 0u) {         // warp-uniform: cheap zero path
                float2* po = reinterpret_cast<float2*>(
                                 out + (size_t)(cellbase + ci) * COUT) + lane;
                __stcs(po, make_float2(0.f, 0.f));
            } else if (pt[ci] != EMPTY16) {
                sfeat[wib][ci][lane] = __ldg(&feat[pt[ci]]);
            }
        }
        __syncwarp();

        // ---- phase 3: hit loops (active cells only; uniform branches) ----
        float A0[CHUNK], A1[CHUNK], MEAN[CHUNK], SQ[CHUNK];
        #pragma unroll
        for (int ci = 0; ci < CHUNK; ci++) {
            if (act[ci] == 0u) continue;
            float a0 = 0.f, a1 = 0.f, mean = 0.f;
            unsigned hits = act[ci];
            while (hits) {
                const int j = __ffs(hits) - 1;
                hits &= hits - 1;
                const float2 fj = sfeat[wib][ci][j];
                const float4* base = &swpx[j][0];
                const float4 wp = base[lane];
                const float4 wb = base[32];          // imm-offset broadcast
                a0 = fmaf(fj.x, wp.x, fmaf(fj.y, wp.z, a0));
                a1 = fmaf(fj.x, wp.y, fmaf(fj.y, wp.w, a1));
                mean = fmaf(fj.x, wb.x, fmaf(fj.y, wb.y, mean));
            }
            A0[ci] = a0; A1[ci] = a1; MEAN[ci] = mean;
            SQ[ci] = a0 * a0 + a1 * a1;
        }

        // ---- phase 4: interleaved butterfly, active cells only ----
        #pragma unroll
        for (int o = 16; o > 0; o >>= 1) {
            #pragma unroll
            for (int ci = 0; ci < CHUNK; ci++)
                if (act[ci] != 0u)
                    SQ[ci] += __shfl_xor_sync(0xffffffffu, SQ[ci], o);
        }

        // ---- phase 5: normalize + relu + streaming store (active only) ----
        #pragma unroll
        for (int ci = 0; ci < CHUNK; ci++) {
            if (act[ci] == 0u) continue;
            const float var = fmaf(-MEAN[ci], MEAN[ci], SQ[ci] * (1.f / COUT));
            const float inv = rsqrtf(var + EPS_LN);
            const float d0 = A0[ci] - MEAN[ci];
            const float d1 = A1[ci] - MEAN[ci];
            const float r0 = fmaxf(fmaf(d0 * inv, gg.x, bb.x), 0.f);
            const float r1 = fmaxf(fmaf(d1 * inv, gg.y, bb.y), 0.f);
            float2* po = reinterpret_cast<float2*>(
                             out + (size_t)(cellbase + ci) * COUT) + lane;
            __stcs(po, make_float2(r0, r1));   // streaming: don't thrash L2
        }
    }
}

// --------------------------------------------------------------------------
extern "C" void kernel_launch(void* const* d_in, const int* in_sizes, int n_in,
                              void* d_out, int out_size) {
    const float* feat   = (const float*)d_in[0];   // [60000, 2]
    const float* weight = (const float*)d_in[1];   // [27, 2, 64]
    const float* gamma  = (const float*)d_in[2];   // [64]
    const float* beta   = (const float*)d_in[3];   // [64]
    const int*   scat   = (const int*)d_in[4];     // [27, 60000]
    float* out = (float*)d_out;                    // [960000, 64]

    init_grid_kernel<<<(CELLS / 4 + 255) / 256, 256>>>();
    fill_grid_kernel<<<(NPTS + 255) / 256, 256>>>(scat);
    wbar_kernel<<<1, 32>>>(weight);
    fused_kernel<<<ROWS_TOTAL, 256>>>(
        (const float2*)feat, (const float2*)weight, gamma, beta, out);
}

// round 13
// speedup vs baseline: 1.3568x; 1.3568x over previous
#include <cuda_runtime.h>
#include <cstdint>

#define NPTS   60000
#define KOFF   27
#define CIN    2
#define COUT   64
#define BB     2
#define DD     12
#define HH     200
#define WW     200
#define CELLS  960000        // 2*12*200*200
#define EPS_LN 1e-5f

#define ROWS_TOTAL (BB * DD * HH)        // 4800 blocks
#define WARPS_PER_BLOCK 8
#define CELLS_PER_WARP  (WW / WARPS_PER_BLOCK)   // 25
#define CHUNK 5                                   // cells processed per phase

#define GROW 202                                  // padded row: [-1 | 200 | -1]

// Dense cell -> point-id lookup grid (3.84 MB, L2-resident). -1 = empty.
__device__ int g_pointgrid[CELLS];
// Channel-mean weight vectors: wbar[j] = (1/64) sum_q w_jq  (2-vec).
__device__ float2 g_wbar[KOFF];

// --------------------------------------------------------------------------
// Kernel 1: init point grid to -1.
// --------------------------------------------------------------------------
__global__ void init_grid_kernel() {
    int i = blockIdx.x * blockDim.x + threadIdx.x;
    if (i < CELLS / 4)
        reinterpret_cast<int4*>(g_pointgrid)[i] = make_int4(-1, -1, -1, -1);
}

// --------------------------------------------------------------------------
// Kernel 2: fill point grid. scat[13*NPTS + n] is point n's own cell index.
// --------------------------------------------------------------------------
__global__ void fill_grid_kernel(const int* __restrict__ scat) {
    int n = blockIdx.x * blockDim.x + threadIdx.x;
    if (n < NPTS)
        g_pointgrid[scat[13 * NPTS + n]] = n;
}

// --------------------------------------------------------------------------
// Kernel 2b: precompute wbar (27 threads, trivial).
// --------------------------------------------------------------------------
__global__ void wbar_kernel(const float* __restrict__ weight) {  // [27,2,64]
    int t = threadIdx.x;
    if (t < KOFF) {
        float s0 = 0.f, s1 = 0.f;
        #pragma unroll 8
        for (int q = 0; q < COUT; q++) {
            s0 += weight[(t * 2 + 0) * COUT + q];
            s1 += weight[(t * 2 + 1) * COUT + q];
        }
        g_wbar[t] = make_float2(s0 * (1.f / COUT), s1 * (1.f / COUT));
    }
}

// --------------------------------------------------------------------------
// Kernel 3: fused gather-conv + LayerNorm + ReLU (R8 layout + uniform skip).
// One block per (b, z, y) row; warp per cell (5-cell chunks). Lane i owns
// channels {2i, 2i+1}. act[ci] is warp-uniform: inactive cells store zeros
// early and skip all later phases with divergence-free branches.
// NOTE: launch_bounds(256, 6) — regs must stay at 40; 7 blocks caused spills.
// --------------------------------------------------------------------------
__global__ __launch_bounds__(256, 6) void fused_kernel(
        const float2* __restrict__ feat,     // [NPTS] as float2
        const float2* __restrict__ weight2,  // float2 view of [27,2,64]
        const float*  __restrict__ gamma,
        const float*  __restrict__ beta,
        float* __restrict__ out) {           // [CELLS, 64]
    __shared__ float4 swpx[KOFF][33];                         // 14256 B
    __shared__ int    sgrid[9 * GROW];                        //  7272 B
    __shared__ float2 sfeat[WARPS_PER_BLOCK][CHUNK][32];      // 10240 B

    // decode row
    const int row = blockIdx.x;          // (b*DD + z)*HH + y
    const int y   = row % HH;
    const int bz  = row / HH;            // b*DD + z
    const int z   = bz % DD;
    const int rowbase = row * WW;        // linear cell index of x=0

    // ---- stage packed weights: swpx[j][lane] = (w0.x, w0.y, w1.x, w1.y) ----
    for (int i = threadIdx.x; i < KOFF * 32; i += blockDim.x) {
        const int j = i >> 5, ln = i & 31;
        const float2 w0 = weight2[(j * 2 + 0) * (COUT / 2) + ln];
        const float2 w1 = weight2[(j * 2 + 1) * (COUT / 2) + ln];
        swpx[j][ln] = make_float4(w0.x, w0.y, w1.x, w1.y);
    }
    if (threadIdx.x < KOFF) {
        const float2 wb = g_wbar[threadIdx.x];
        swpx[threadIdx.x][32] = make_float4(wb.x, wb.y, 0.f, 0.f);
    }

    // ---- stage 9 neighbor grid rows with halo ----
    for (int i = threadIdx.x; i < 9 * GROW; i += blockDim.x) {
        const int r  = i / GROW;         // 0..8 -> (dz+1)*3 + (dy+1)
        const int c  = i - r * GROW;     // 0..201 -> x = c-1
        const int dz = r / 3 - 1;
        const int dy = r % 3 - 1;
        const int nz = z + dz, ny = y + dy, nx = c - 1;
        int v = -1;
        if ((unsigned)nz < DD && (unsigned)ny < HH && (unsigned)nx < WW)
            v = g_pointgrid[rowbase + (dz * HH + dy) * WW + nx];
        sgrid[i] = v;
    }
    __syncthreads();

    const int lane = threadIdx.x & 31;
    const int wib  = threadIdx.x >> 5;

    const float2 gg = reinterpret_cast<const float2*>(gamma)[lane];
    const float2 bb = reinterpret_cast<const float2*>(beta)[lane];

    // lane -> (k, smem probe base)
    const int dxl   = lane % 3;                         // dx+1 for lanes<27
    const int srow  = (lane < KOFF) ? (lane / 3) : 0;   // (dz+1)*3+(dy+1)
    const int pbase = srow * GROW + dxl;                // + x gives probe index
    const bool probing = (lane < KOFF);

    const int x0 = wib * CELLS_PER_WARP;

    for (int c0 = 0; c0 < CELLS_PER_WARP; c0 += CHUNK) {
        // ---- phase 1: probes (LDS) ----
        int pt[CHUNK];
        #pragma unroll
        for (int ci = 0; ci < CHUNK; ci++) {
            const int x = x0 + c0 + ci;
            pt[ci] = probing ? sgrid[pbase + x] : -1;
        }

        // ---- phase 2: ballots; inactive cells -> zero store, skip rest ----
        unsigned act[CHUNK];
        #pragma unroll
        for (int ci = 0; ci < CHUNK; ci++)
            act[ci] = __ballot_sync(0xffffffffu, pt[ci] >= 0);

        const int cellbase = rowbase + x0 + c0;
        #pragma unroll
        for (int ci = 0; ci < CHUNK; ci++) {
            if (act[ci] == 0u) {             // warp-uniform branch
                float2* po = reinterpret_cast<float2*>(
                                 out + (size_t)(cellbase + ci) * COUT) + lane;
                __stcs(po, make_float2(0.f, 0.f));
            } else if (pt[ci] >= 0) {
                sfeat[wib][ci][lane] = __ldg(&feat[pt[ci]]);
            }
        }
        __syncwarp();

        // ---- phase 3: accumulate channels + analytic mean (active only) ----
        float A0[CHUNK], A1[CHUNK], MEAN[CHUNK], SQ[CHUNK];
        #pragma unroll
        for (int ci = 0; ci < CHUNK; ci++) {
            if (act[ci] == 0u) continue;     // warp-uniform
            float a0 = 0.f, a1 = 0.f, mean = 0.f;
            unsigned hits = act[ci];
            while (hits) {
                const int j = __ffs(hits) - 1;
                hits &= hits - 1;
                const float2 fj = sfeat[wib][ci][j];
                const float4* base = &swpx[j][0];
                const float4 wp = base[lane];
                const float4 wb = base[32];          // imm-offset LDS, broadcast
                a0 = fmaf(fj.x, wp.x, fmaf(fj.y, wp.z, a0));
                a1 = fmaf(fj.x, wp.y, fmaf(fj.y, wp.w, a1));
                mean = fmaf(fj.x, wb.x, fmaf(fj.y, wb.y, mean));
            }
            A0[ci] = a0; A1[ci] = a1; MEAN[ci] = mean;
            SQ[ci] = a0 * a0 + a1 * a1;
        }

        // ---- phase 4: interleaved butterfly (active cells only) ----
        #pragma unroll
        for (int o = 16; o > 0; o >>= 1) {
            #pragma unroll
            for (int ci = 0; ci < CHUNK; ci++)
                if (act[ci] != 0u)
                    SQ[ci] += __shfl_xor_sync(0xffffffffu, SQ[ci], o);
        }

        // ---- phase 5: normalize + relu + streaming store (active only) ----
        #pragma unroll
        for (int ci = 0; ci < CHUNK; ci++) {
            if (act[ci] == 0u) continue;     // warp-uniform
            const float var = fmaf(-MEAN[ci], MEAN[ci], SQ[ci] * (1.f / COUT));
            const float inv = rsqrtf(var + EPS_LN);
            const float d0 = A0[ci] - MEAN[ci];
            const float d1 = A1[ci] - MEAN[ci];
            const float r0 = fmaxf(fmaf(d0 * inv, gg.x, bb.x), 0.f);
            const float r1 = fmaxf(fmaf(d1 * inv, gg.y, bb.y), 0.f);
            float2* po = reinterpret_cast<float2*>(
                             out + (size_t)(cellbase + ci) * COUT) + lane;
            __stcs(po, make_float2(r0, r1));   // streaming: don't thrash L2
        }
    }
}

// --------------------------------------------------------------------------
extern "C" void kernel_launch(void* const* d_in, const int* in_sizes, int n_in,
                              void* d_out, int out_size) {
    const float* feat   = (const float*)d_in[0];   // [60000, 2]
    const float* weight = (const float*)d_in[1];   // [27, 2, 64]
    const float* gamma  = (const float*)d_in[2];   // [64]
    const float* beta   = (const float*)d_in[3];   // [64]
    const int*   scat   = (const int*)d_in[4];     // [27, 60000]
    float* out = (float*)d_out;                    // [960000, 64]

    init_grid_kernel<<<(CELLS / 4 + 255) / 256, 256>>>();
    fill_grid_kernel<<<(NPTS + 255) / 256, 256>>>(scat);
    wbar_kernel<<<1, 32>>>(weight);
    fused_kernel<<<ROWS_TOTAL, 256>>>(
        (const float2*)feat, (const float2*)weight, gamma, beta, out);
}

// round 14
// speedup vs baseline: 1.6476x; 1.2143x over previous
#include <cuda_runtime.h>
#include <cstdint>

#define NPTS   60000
#define KOFF   27
#define CIN    2
#define COUT   64
#define BB     2
#define DD     12
#define HH     200
#define WW     200
#define CELLS  960000        // 2*12*200*200
#define EPS_LN 1e-5f

#define ROWS_TOTAL (BB * DD * HH)        // 4800 blocks
#define WARPS_PER_BLOCK 8
#define CELLS_PER_WARP  (WW / WARPS_PER_BLOCK)   // 25
#define CHUNK 5                                   // cells processed per phase

#define GROW 202                                  // padded row: [-1 | 200 | -1]

// Dense cell -> point-id lookup grid (3.84 MB, L2-resident). -1 = empty.
__device__ int g_pointgrid[CELLS];
// Channel-mean weight vectors: wbar[j] = (1/64) sum_q w_jq  (2-vec).
__device__ float2 g_wbar[KOFF];

// Packed helpers (free mov.b64 pack/unpack on register pairs + f32x2 add).
__device__ __forceinline__ unsigned long long pack2(float a, float b) {
    unsigned long long p;
    asm("mov.b64 %0, {%1, %2};" : "=l"(p) : "f"(a), "f"(b));
    return p;
}
__device__ __forceinline__ void unpack2(unsigned long long p, float& a, float& b) {
    asm("mov.b64 {%0, %1}, %2;" : "=f"(a), "=f"(b) : "l"(p));
}
__device__ __forceinline__ unsigned long long addf32x2(unsigned long long a,
                                                       unsigned long long b) {
    unsigned long long d;
    asm("add.rn.f32x2 %0, %1, %2;" : "=l"(d) : "l"(a), "l"(b));
    return d;
}

// --------------------------------------------------------------------------
// Kernel 1: init point grid to -1.
// --------------------------------------------------------------------------
__global__ void init_grid_kernel() {
    int i = blockIdx.x * blockDim.x + threadIdx.x;
    if (i < CELLS / 4)
        reinterpret_cast<int4*>(g_pointgrid)[i] = make_int4(-1, -1, -1, -1);
}

// --------------------------------------------------------------------------
// Kernel 2: fill point grid. scat[13*NPTS + n] is point n's own cell index.
// --------------------------------------------------------------------------
__global__ void fill_grid_kernel(const int* __restrict__ scat) {
    int n = blockIdx.x * blockDim.x + threadIdx.x;
    if (n < NPTS)
        g_pointgrid[scat[13 * NPTS + n]] = n;
}

// --------------------------------------------------------------------------
// Kernel 2b: precompute wbar (27 threads, trivial).
// --------------------------------------------------------------------------
__global__ void wbar_kernel(const float* __restrict__ weight) {  // [27,2,64]
    int t = threadIdx.x;
    if (t < KOFF) {
        float s0 = 0.f, s1 = 0.f;
        #pragma unroll 8
        for (int q = 0; q < COUT; q++) {
            s0 += weight[(t * 2 + 0) * COUT + q];
            s1 += weight[(t * 2 + 1) * COUT + q];
        }
        g_wbar[t] = make_float2(s0 * (1.f / COUT), s1 * (1.f / COUT));
    }
}

// --------------------------------------------------------------------------
// Kernel 3: fused gather-conv + LayerNorm + ReLU (proven R8 structure).
// One block per (b, z, y) row; warp per cell (5-cell chunks). Lane i owns
// channels {2i, 2i+1}. mean analytic via wbar (merged into weight table);
// var via one interleaved butterfly (packed f32x2 adds). All phases
// straight-line, no per-cell branches. Stores use chunk-base + imm offsets.
// --------------------------------------------------------------------------
__global__ __launch_bounds__(256, 6) void fused_kernel(
        const float2* __restrict__ feat,     // [NPTS] as float2
        const float2* __restrict__ weight2,  // float2 view of [27,2,64]
        const float*  __restrict__ gamma,
        const float*  __restrict__ beta,
        float* __restrict__ out) {           // [CELLS, 64]
    __shared__ float4 swpx[KOFF][33];                         // 14256 B
    __shared__ int    sgrid[9 * GROW];                        //  7272 B
    __shared__ float2 sfeat[WARPS_PER_BLOCK][CHUNK][32];      // 10240 B

    // decode row
    const int row = blockIdx.x;          // (b*DD + z)*HH + y
    const int y   = row % HH;
    const int bz  = row / HH;            // b*DD + z
    const int z   = bz % DD;
    const int rowbase = row * WW;        // linear cell index of x=0

    // ---- stage packed weights: swpx[j][lane] = (w0.x, w0.y, w1.x, w1.y) ----
    for (int i = threadIdx.x; i < KOFF * 32; i += blockDim.x) {
        const int j = i >> 5, ln = i & 31;
        const float2 w0 = weight2[(j * 2 + 0) * (COUT / 2) + ln];
        const float2 w1 = weight2[(j * 2 + 1) * (COUT / 2) + ln];
        swpx[j][ln] = make_float4(w0.x, w0.y, w1.x, w1.y);
    }
    if (threadIdx.x < KOFF) {
        const float2 wb = g_wbar[threadIdx.x];
        swpx[threadIdx.x][32] = make_float4(wb.x, wb.y, 0.f, 0.f);
    }

    // ---- stage 9 neighbor grid rows with halo ----
    for (int i = threadIdx.x; i < 9 * GROW; i += blockDim.x) {
        const int r  = i / GROW;         // 0..8 -> (dz+1)*3 + (dy+1)
        const int c  = i - r * GROW;     // 0..201 -> x = c-1
        const int dz = r / 3 - 1;
        const int dy = r % 3 - 1;
        const int nz = z + dz, ny = y + dy, nx = c - 1;
        int v = -1;
        if ((unsigned)nz < DD && (unsigned)ny < HH && (unsigned)nx < WW)
            v = g_pointgrid[rowbase + (dz * HH + dy) * WW + nx];
        sgrid[i] = v;
    }
    __syncthreads();

    const int lane = threadIdx.x & 31;
    const int wib  = threadIdx.x >> 5;

    const float2 gg = reinterpret_cast<const float2*>(gamma)[lane];
    const float2 bb = reinterpret_cast<const float2*>(beta)[lane];

    // lane -> (k, smem probe base)
    const int dxl   = lane % 3;                         // dx+1 for lanes<27
    const int srow  = (lane < KOFF) ? (lane / 3) : 0;   // (dz+1)*3+(dy+1)
    const int pbase = srow * GROW + dxl;                // + x gives probe index
    const bool probing = (lane < KOFF);

    const int x0 = wib * CELLS_PER_WARP;

    for (int c0 = 0; c0 < CELLS_PER_WARP; c0 += CHUNK) {
        // ---- phase 1: probes (LDS) ----
        int pt[CHUNK];
        #pragma unroll
        for (int ci = 0; ci < CHUNK; ci++) {
            const int x = x0 + c0 + ci;
            pt[ci] = probing ? sgrid[pbase + x] : -1;
        }

        // ---- phase 2: ballots + feature gather -> smem bounce ----
        unsigned act[CHUNK];
        #pragma unroll
        for (int ci = 0; ci < CHUNK; ci++)
            act[ci] = __ballot_sync(0xffffffffu, pt[ci] >= 0);
        #pragma unroll
        for (int ci = 0; ci < CHUNK; ci++)
            if (pt[ci] >= 0)
                sfeat[wib][ci][lane] = __ldg(&feat[pt[ci]]);
        __syncwarp();

        // ---- phase 3: accumulate channels + analytic mean ----
        float A0[CHUNK], A1[CHUNK], MEAN[CHUNK], SQ[CHUNK];
        #pragma unroll
        for (int ci = 0; ci < CHUNK; ci++) {
            float a0 = 0.f, a1 = 0.f, mean = 0.f;
            unsigned hits = act[ci];
            while (hits) {
                const int j = __ffs(hits) - 1;
                hits &= hits - 1;
                const float2 fj = sfeat[wib][ci][j];
                const float4* base = &swpx[j][0];
                const float4 wp = base[lane];
                const float4 wb = base[32];          // imm-offset LDS, broadcast
                a0 = fmaf(fj.x, wp.x, fmaf(fj.y, wp.z, a0));
                a1 = fmaf(fj.x, wp.y, fmaf(fj.y, wp.w, a1));
                mean = fmaf(fj.x, wb.x, fmaf(fj.y, wb.y, mean));
            }
            A0[ci] = a0; A1[ci] = a1; MEAN[ci] = mean;
            SQ[ci] = a0 * a0 + a1 * a1;
        }

        // ---- phase 4: interleaved butterfly, packed f32x2 adds ----
        {
            unsigned long long p01 = pack2(SQ[0], SQ[1]);
            unsigned long long p23 = pack2(SQ[2], SQ[3]);
            float s4 = SQ[4];
            #pragma unroll
            for (int o = 16; o > 0; o >>= 1) {
                const unsigned long long q01 =
                    __shfl_xor_sync(0xffffffffu, p01, o);
                const unsigned long long q23 =
                    __shfl_xor_sync(0xffffffffu, p23, o);
                const float t4 = __shfl_xor_sync(0xffffffffu, s4, o);
                p01 = addf32x2(p01, q01);
                p23 = addf32x2(p23, q23);
                s4 += t4;
            }
            unpack2(p01, SQ[0], SQ[1]);
            unpack2(p23, SQ[2], SQ[3]);
            SQ[4] = s4;
        }

        // ---- phase 5: normalize + relu + streaming store (imm offsets) ----
        float2* chunkout = reinterpret_cast<float2*>(
                               out + (size_t)(rowbase + x0 + c0) * COUT) + lane;
        #pragma unroll
        for (int ci = 0; ci < CHUNK; ci++) {
            const float var = fmaf(-MEAN[ci], MEAN[ci], SQ[ci] * (1.f / COUT));
            const float inv = rsqrtf(var + EPS_LN);
            const float d0 = A0[ci] - MEAN[ci];
            const float d1 = A1[ci] - MEAN[ci];
            float r0 = fmaxf(fmaf(d0 * inv, gg.x, bb.x), 0.f);
            float r1 = fmaxf(fmaf(d1 * inv, gg.y, bb.y), 0.f);
            if (act[ci] == 0u) { r0 = 0.f; r1 = 0.f; }
            __stcs(chunkout + ci * (COUT / 2), make_float2(r0, r1));
        }
    }
}

// --------------------------------------------------------------------------
extern "C" void kernel_launch(void* const* d_in, const int* in_sizes, int n_in,
                              void* d_out, int out_size) {
    const float* feat   = (const float*)d_in[0];   // [60000, 2]
    const float* weight = (const float*)d_in[1];   // [27, 2, 64]
    const float* gamma  = (const float*)d_in[2];   // [64]
    const float* beta   = (const float*)d_in[3];   // [64]
    const int*   scat   = (const int*)d_in[4];     // [27, 60000]
    float* out = (float*)d_out;                    // [960000, 64]

    init_grid_kernel<<<(CELLS / 4 + 255) / 256, 256>>>();
    fill_grid_kernel<<<(NPTS + 255) / 256, 256>>>(scat);
    wbar_kernel<<<1, 32>>>(weight);
    fused_kernel<<<ROWS_TOTAL, 256>>>(
        (const float2*)feat, (const float2*)weight, gamma, beta, out);
}

// round 15
// speedup vs baseline: 1.7958x; 1.0899x over previous
#include <cuda_runtime.h>
#include <cstdint>

#define NPTS   60000
#define KOFF   27
#define CIN    2
#define COUT   64
#define BB     2
#define DD     12
#define HH     200
#define WW     200
#define CELLS  960000        // 2*12*200*200
#define EPS_LN 1e-5f

#define ROWS_TOTAL (BB * DD * HH)        // 4800 blocks
#define WARPS_PER_BLOCK 8
#define CELLS_PER_WARP  (WW / WARPS_PER_BLOCK)   // 25
#define CHUNK 5                                   // cells processed per phase

#define GROW 202                                  // padded row: [-1 | 200 | -1]

// Dense cell -> point-id lookup grid (3.84 MB, L2-resident). -1 = empty.
__device__ int g_pointgrid[CELLS];
// Centered weights: wc[j,cin,q] = w[j,cin,q] - (1/64) sum_q' w[j,cin,q'].
// With centered weights, accumulated channels are already mean-subtracted.
__device__ float g_wc[KOFF * CIN * COUT];

// Packed helpers (free mov.b64 pack/unpack on register pairs + f32x2 add).
__device__ __forceinline__ unsigned long long pack2(float a, float b) {
    unsigned long long p;
    asm("mov.b64 %0, {%1, %2};" : "=l"(p) : "f"(a), "f"(b));
    return p;
}
__device__ __forceinline__ void unpack2(unsigned long long p, float& a, float& b) {
    asm("mov.b64 {%0, %1}, %2;" : "=f"(a), "=f"(b) : "l"(p));
}
__device__ __forceinline__ unsigned long long addf32x2(unsigned long long a,
                                                       unsigned long long b) {
    unsigned long long d;
    asm("add.rn.f32x2 %0, %1, %2;" : "=l"(d) : "l"(a), "l"(b));
    return d;
}

// --------------------------------------------------------------------------
// Kernel 1: init point grid to -1.
// --------------------------------------------------------------------------
__global__ void init_grid_kernel() {
    int i = blockIdx.x * blockDim.x + threadIdx.x;
    if (i < CELLS / 4)
        reinterpret_cast<int4*>(g_pointgrid)[i] = make_int4(-1, -1, -1, -1);
}

// --------------------------------------------------------------------------
// Kernel 2: fill point grid. scat[13*NPTS + n] is point n's own cell index.
// --------------------------------------------------------------------------
__global__ void fill_grid_kernel(const int* __restrict__ scat) {
    int n = blockIdx.x * blockDim.x + threadIdx.x;
    if (n < NPTS)
        g_pointgrid[scat[13 * NPTS + n]] = n;
}

// --------------------------------------------------------------------------
// Kernel 2b: precompute centered weights (one block, trivial).
// --------------------------------------------------------------------------
__global__ void center_weights_kernel(const float* __restrict__ weight) { // [27,2,64]
    __shared__ float sbar[KOFF * CIN];
    const int t = threadIdx.x;
    if (t < KOFF * CIN) {
        float s = 0.f;
        #pragma unroll 8
        for (int q = 0; q < COUT; q++)
            s += weight[t * COUT + q];
        sbar[t] = s * (1.f / COUT);
    }
    __syncthreads();
    for (int i = t; i < KOFF * CIN * COUT; i += blockDim.x)
        g_wc[i] = weight[i] - sbar[i / COUT];
}

// --------------------------------------------------------------------------
// Kernel 3: fused gather-conv + LayerNorm + ReLU (R13 structure, centered w).
// One block per (b, z, y) row; warp per cell (5-cell chunks). Lane i owns
// channels {2i, 2i+1}. Accumulators are mean-free by construction, so
// var = sum(a'^2)/64 via one interleaved butterfly (packed f32x2 adds).
// Straight-line phases; stores use chunk-base + imm offsets.
// --------------------------------------------------------------------------
__global__ __launch_bounds__(256, 6) void fused_kernel(
        const float2* __restrict__ feat,     // [NPTS] as float2
        const float*  __restrict__ gamma,
        const float*  __restrict__ beta,
        float* __restrict__ out) {           // [CELLS, 64]
    __shared__ float4 swpx[KOFF][33];                         // 14256 B
    __shared__ int    sgrid[9 * GROW];                        //  7272 B
    __shared__ float2 sfeat[WARPS_PER_BLOCK][CHUNK][32];      // 10240 B

    // decode row
    const int row = blockIdx.x;          // (b*DD + z)*HH + y
    const int y   = row % HH;
    const int bz  = row / HH;            // b*DD + z
    const int z   = bz % DD;
    const int rowbase = row * WW;        // linear cell index of x=0

    // ---- stage centered weights: swpx[j][ln] = (w0.x, w0.y, w1.x, w1.y) ----
    const float2* wc2 = reinterpret_cast<const float2*>(g_wc);
    for (int i = threadIdx.x; i < KOFF * 32; i += blockDim.x) {
        const int j = i >> 5, ln = i & 31;
        const float2 w0 = wc2[(j * 2 + 0) * (COUT / 2) + ln];
        const float2 w1 = wc2[(j * 2 + 1) * (COUT / 2) + ln];
        swpx[j][ln] = make_float4(w0.x, w0.y, w1.x, w1.y);
    }

    // ---- stage 9 neighbor grid rows with halo ----
    for (int i = threadIdx.x; i < 9 * GROW; i += blockDim.x) {
        const int r  = i / GROW;         // 0..8 -> (dz+1)*3 + (dy+1)
        const int c  = i - r * GROW;     // 0..201 -> x = c-1
        const int dz = r / 3 - 1;
        const int dy = r % 3 - 1;
        const int nz = z + dz, ny = y + dy, nx = c - 1;
        int v = -1;
        if ((unsigned)nz < DD && (unsigned)ny < HH && (unsigned)nx < WW)
            v = g_pointgrid[rowbase + (dz * HH + dy) * WW + nx];
        sgrid[i] = v;
    }
    __syncthreads();

    const int lane = threadIdx.x & 31;
    const int wib  = threadIdx.x >> 5;

    const float2 gg = reinterpret_cast<const float2*>(gamma)[lane];
    const float2 bb = reinterpret_cast<const float2*>(beta)[lane];

    // lane -> (k, smem probe base)
    const int dxl   = lane % 3;                         // dx+1 for lanes<27
    const int srow  = (lane < KOFF) ? (lane / 3) : 0;   // (dz+1)*3+(dy+1)
    const int pbase = srow * GROW + dxl;                // + x gives probe index
    const bool probing = (lane < KOFF);

    const int x0 = wib * CELLS_PER_WARP;

    for (int c0 = 0; c0 < CELLS_PER_WARP; c0 += CHUNK) {
        // ---- phase 1: probes (LDS) ----
        int pt[CHUNK];
        #pragma unroll
        for (int ci = 0; ci < CHUNK; ci++) {
            const int x = x0 + c0 + ci;
            pt[ci] = probing ? sgrid[pbase + x] : -1;
        }

        // ---- phase 2: ballots + feature gather -> smem bounce ----
        unsigned act[CHUNK];
        #pragma unroll
        for (int ci = 0; ci < CHUNK; ci++)
            act[ci] = __ballot_sync(0xffffffffu, pt[ci] >= 0);
        #pragma unroll
        for (int ci = 0; ci < CHUNK; ci++)
            if (pt[ci] >= 0)
                sfeat[wib][ci][lane] = __ldg(&feat[pt[ci]]);
        __syncwarp();

        // ---- phase 3: accumulate centered channels ----
        float A0[CHUNK], A1[CHUNK], SQ[CHUNK];
        #pragma unroll
        for (int ci = 0; ci < CHUNK; ci++) {
            float a0 = 0.f, a1 = 0.f;
            unsigned hits = act[ci];
            while (hits) {
                const int j = __ffs(hits) - 1;
                hits &= hits - 1;
                const float2 fj = sfeat[wib][ci][j];
                const float4 wp = swpx[j][lane];
                a0 = fmaf(fj.x, wp.x, fmaf(fj.y, wp.z, a0));
                a1 = fmaf(fj.x, wp.y, fmaf(fj.y, wp.w, a1));
            }
            A0[ci] = a0; A1[ci] = a1;
            SQ[ci] = a0 * a0 + a1 * a1;
        }

        // ---- phase 4: interleaved butterfly, packed f32x2 adds ----
        {
            unsigned long long p01 = pack2(SQ[0], SQ[1]);
            unsigned long long p23 = pack2(SQ[2], SQ[3]);
            float s4 = SQ[4];
            #pragma unroll
            for (int o = 16; o > 0; o >>= 1) {
                const unsigned long long q01 =
                    __shfl_xor_sync(0xffffffffu, p01, o);
                const unsigned long long q23 =
                    __shfl_xor_sync(0xffffffffu, p23, o);
                const float t4 = __shfl_xor_sync(0xffffffffu, s4, o);
                p01 = addf32x2(p01, q01);
                p23 = addf32x2(p23, q23);
                s4 += t4;
            }
            unpack2(p01, SQ[0], SQ[1]);
            unpack2(p23, SQ[2], SQ[3]);
            SQ[4] = s4;
        }

        // ---- phase 5: normalize + relu + streaming store (imm offsets) ----
        float2* chunkout = reinterpret_cast<float2*>(
                               out + (size_t)(rowbase + x0 + c0) * COUT) + lane;
        #pragma unroll
        for (int ci = 0; ci < CHUNK; ci++) {
            const float inv = rsqrtf(fmaf(SQ[ci], (1.f / COUT), EPS_LN));
            float r0 = fmaxf(fmaf(A0[ci] * inv, gg.x, bb.x), 0.f);
            float r1 = fmaxf(fmaf(A1[ci] * inv, gg.y, bb.y), 0.f);
            if (act[ci] == 0u) { r0 = 0.f; r1 = 0.f; }
            __stcs(chunkout + ci * (COUT / 2), make_float2(r0, r1));
        }
    }
}

// --------------------------------------------------------------------------
extern "C" void kernel_launch(void* const* d_in, const int* in_sizes, int n_in,
                              void* d_out, int out_size) {
    const float* feat   = (const float*)d_in[0];   // [60000, 2]
    const float* weight = (const float*)d_in[1];   // [27, 2, 64]
    const float* gamma  = (const float*)d_in[2];   // [64]
    const float* beta   = (const float*)d_in[3];   // [64]
    const int*   scat   = (const int*)d_in[4];     // [27, 60000]
    float* out = (float*)d_out;                    // [960000, 64]

    init_grid_kernel<<<(CELLS / 4 + 255) / 256, 256>>>();
    fill_grid_kernel<<<(NPTS + 255) / 256, 256>>>(scat);
    center_weights_kernel<<<1, 256>>>(weight);
    fused_kernel<<<ROWS_TOTAL, 256>>>(
        (const float2*)feat, gamma, beta, out);
}

// round 16
// speedup vs baseline: 1.8179x; 1.0123x over previous
#include <cuda_runtime.h>
#include <cstdint>
#include <math_constants.h>

#define NPTS   60000
#define KOFF   27
#define CIN    2
#define COUT   64
#define BB     2
#define DD     12
#define HH     200
#define WW     200
#define CELLS  960000        // 2*12*200*200
#define EPS_LN 1e-5f

#define ROWS_TOTAL (BB * DD * HH)        // 4800 blocks
#define WARPS_PER_BLOCK 8
#define CELLS_PER_WARP  (WW / WARPS_PER_BLOCK)   // 25
#define CHUNK 5                                   // cells processed per phase

#define GROW 202                                  // padded row: [-1 | 200 | -1]

// Dense cell -> feature grid (7.7 MB, L2-resident). x = NaN marks empty.
__device__ float2 g_featgrid[CELLS];
// Centered weights: wc[j,cin,q] = w[j,cin,q] - (1/64) sum_q' w[j,cin,q'].
__device__ float g_wc[KOFF * CIN * COUT];

// Packed helpers (free mov.b64 pack/unpack on register pairs + f32x2 add).
__device__ __forceinline__ unsigned long long pack2(float a, float b) {
    unsigned long long p;
    asm("mov.b64 %0, {%1, %2};" : "=l"(p) : "f"(a), "f"(b));
    return p;
}
__device__ __forceinline__ void unpack2(unsigned long long p, float& a, float& b) {
    asm("mov.b64 {%0, %1}, %2;" : "=f"(a), "=f"(b) : "l"(p));
}
__device__ __forceinline__ unsigned long long addf32x2(unsigned long long a,
                                                       unsigned long long b) {
    unsigned long long d;
    asm("add.rn.f32x2 %0, %1, %2;" : "=l"(d) : "l"(a), "l"(b));
    return d;
}

// --------------------------------------------------------------------------
// Kernel 1: init feature grid to (NaN, NaN).
// --------------------------------------------------------------------------
__global__ void init_grid_kernel() {
    const float nanf_ = CUDART_NAN_F;
    int i = blockIdx.x * blockDim.x + threadIdx.x;
    if (i < CELLS / 2)
        reinterpret_cast<float4*>(g_featgrid)[i] =
            make_float4(nanf_, nanf_, nanf_, nanf_);
}

// --------------------------------------------------------------------------
// Kernel 2: fill feature grid. scat[13*NPTS + n] is point n's own cell.
// --------------------------------------------------------------------------
__global__ void fill_grid_kernel(const int* __restrict__ scat,
                                 const float2* __restrict__ feat) {
    int n = blockIdx.x * blockDim.x + threadIdx.x;
    if (n < NPTS)
        g_featgrid[scat[13 * NPTS + n]] = feat[n];
}

// --------------------------------------------------------------------------
// Kernel 2b: precompute centered weights (one block, trivial).
// --------------------------------------------------------------------------
__global__ void center_weights_kernel(const float* __restrict__ weight) { // [27,2,64]
    __shared__ float sbar[KOFF * CIN];
    const int t = threadIdx.x;
    if (t < KOFF * CIN) {
        float s = 0.f;
        #pragma unroll 8
        for (int q = 0; q < COUT; q++)
            s += weight[t * COUT + q];
        sbar[t] = s * (1.f / COUT);
    }
    __syncthreads();
    for (int i = t; i < KOFF * CIN * COUT; i += blockDim.x)
        g_wc[i] = weight[i] - sbar[i / COUT];
}

// --------------------------------------------------------------------------
// Kernel 3: fused gather-conv + LayerNorm + ReLU.
// One block per (b, z, y) row; 9 neighbor FEATURE rows staged in smem with
// halo (NaN = empty) -> probe IS the gather, no per-hit global loads.
// Warp per cell (5-cell chunks); lane i owns channels {2i, 2i+1}.
// Centered weights make accumulators mean-free; var = sum(a^2)/64 via one
// interleaved butterfly. Straight-line phases; imm-offset streaming stores.
// --------------------------------------------------------------------------
__global__ __launch_bounds__(256, 6) void fused_kernel(
        const float*  __restrict__ gamma,
        const float*  __restrict__ beta,
        float* __restrict__ out) {           // [CELLS, 64]
    __shared__ float4 swpx[KOFF][32];                         // 13824 B
    __shared__ float2 sfg[9 * GROW];                          // 14544 B
    __shared__ float2 sfeat[WARPS_PER_BLOCK][CHUNK][28];      //  8960 B

    // decode row
    const int row = blockIdx.x;          // (b*DD + z)*HH + y
    const int y   = row % HH;
    const int bz  = row / HH;            // b*DD + z
    const int z   = bz % DD;
    const int rowbase = row * WW;        // linear cell index of x=0

    // ---- stage centered weights: swpx[j][ln] = (w0.x, w0.y, w1.x, w1.y) ----
    const float2* wc2 = reinterpret_cast<const float2*>(g_wc);
    for (int i = threadIdx.x; i < KOFF * 32; i += blockDim.x) {
        const int j = i >> 5, ln = i & 31;
        const float2 w0 = wc2[(j * 2 + 0) * (COUT / 2) + ln];
        const float2 w1 = wc2[(j * 2 + 1) * (COUT / 2) + ln];
        swpx[j][ln] = make_float4(w0.x, w0.y, w1.x, w1.y);
    }

    // ---- stage 9 neighbor FEATURE rows with halo (NaN = empty/OOB) ----
    for (int i = threadIdx.x; i < 9 * GROW; i += blockDim.x) {
        const int r  = i / GROW;         // 0..8 -> (dz+1)*3 + (dy+1)
        const int c  = i - r * GROW;     // 0..201 -> x = c-1
        const int dz = r / 3 - 1;
        const int dy = r % 3 - 1;
        const int nz = z + dz, ny = y + dy, nx = c - 1;
        float2 v = make_float2(CUDART_NAN_F, CUDART_NAN_F);
        if ((unsigned)nz < DD && (unsigned)ny < HH && (unsigned)nx < WW)
            v = g_featgrid[rowbase + (dz * HH + dy) * WW + nx];
        sfg[i] = v;
    }
    __syncthreads();

    const int lane = threadIdx.x & 31;
    const int wib  = threadIdx.x >> 5;

    const float2 gg = reinterpret_cast<const float2*>(gamma)[lane];
    const float2 bb = reinterpret_cast<const float2*>(beta)[lane];

    // lane -> (k, smem probe base)
    const int dxl   = lane % 3;                         // dx+1 for lanes<27
    const int srow  = (lane < KOFF) ? (lane / 3) : 0;   // (dz+1)*3+(dy+1)
    const int pbase = srow * GROW + dxl;                // + x gives probe index
    const bool probing = (lane < KOFF);

    const int x0 = wib * CELLS_PER_WARP;

    for (int c0 = 0; c0 < CELLS_PER_WARP; c0 += CHUNK) {
        // ---- phase 1: probes return features directly (LDS.64) ----
        float2 f[CHUNK];
        #pragma unroll
        for (int ci = 0; ci < CHUNK; ci++) {
            const int x = x0 + c0 + ci;
            f[ci] = probing ? sfg[pbase + x]
                            : make_float2(CUDART_NAN_F, CUDART_NAN_F);
        }

        // ---- phase 2: ballots + in-register bounce to compact smem ----
        unsigned act[CHUNK];
        #pragma unroll
        for (int ci = 0; ci < CHUNK; ci++)
            act[ci] = __ballot_sync(0xffffffffu, f[ci].x == f[ci].x);
        #pragma unroll
        for (int ci = 0; ci < CHUNK; ci++)
            if (f[ci].x == f[ci].x)
                sfeat[wib][ci][lane] = f[ci];
        __syncwarp();

        // ---- phase 3: accumulate centered channels ----
        float A0[CHUNK], A1[CHUNK], SQ[CHUNK];
        #pragma unroll
        for (int ci = 0; ci < CHUNK; ci++) {
            float a0 = 0.f, a1 = 0.f;
            unsigned hits = act[ci];
            while (hits) {
                const int j = __ffs(hits) - 1;
                hits &= hits - 1;
                const float2 fj = sfeat[wib][ci][j];
                const float4 wp = swpx[j][lane];
                a0 = fmaf(fj.x, wp.x, fmaf(fj.y, wp.z, a0));
                a1 = fmaf(fj.x, wp.y, fmaf(fj.y, wp.w, a1));
            }
            A0[ci] = a0; A1[ci] = a1;
            SQ[ci] = a0 * a0 + a1 * a1;
        }

        // ---- phase 4: interleaved butterfly, packed f32x2 adds ----
        {
            unsigned long long p01 = pack2(SQ[0], SQ[1]);
            unsigned long long p23 = pack2(SQ[2], SQ[3]);
            float s4 = SQ[4];
            #pragma unroll
            for (int o = 16; o > 0; o >>= 1) {
                const unsigned long long q01 =
                    __shfl_xor_sync(0xffffffffu, p01, o);
                const unsigned long long q23 =
                    __shfl_xor_sync(0xffffffffu, p23, o);
                const float t4 = __shfl_xor_sync(0xffffffffu, s4, o);
                p01 = addf32x2(p01, q01);
                p23 = addf32x2(p23, q23);
                s4 += t4;
            }
            unpack2(p01, SQ[0], SQ[1]);
            unpack2(p23, SQ[2], SQ[3]);
            SQ[4] = s4;
        }

        // ---- phase 5: normalize + relu + streaming store (imm offsets) ----
        float2* chunkout = reinterpret_cast<float2*>(
                               out + (size_t)(rowbase + x0 + c0) * COUT) + lane;
        #pragma unroll
        for (int ci = 0; ci < CHUNK; ci++) {
            const float inv = rsqrtf(fmaf(SQ[ci], (1.f / COUT), EPS_LN));
            float r0 = fmaxf(fmaf(A0[ci] * inv, gg.x, bb.x), 0.f);
            float r1 = fmaxf(fmaf(A1[ci] * inv, gg.y, bb.y), 0.f);
            if (act[ci] == 0u) { r0 = 0.f; r1 = 0.f; }
            __stcs(chunkout + ci * (COUT / 2), make_float2(r0, r1));
        }
    }
}

// --------------------------------------------------------------------------
extern "C" void kernel_launch(void* const* d_in, const int* in_sizes, int n_in,
                              void* d_out, int out_size) {
    const float* feat   = (const float*)d_in[0];   // [60000, 2]
    const float* weight = (const float*)d_in[1];   // [27, 2, 64]
    const float* gamma  = (const float*)d_in[2];   // [64]
    const float* beta   = (const float*)d_in[3];   // [64]
    const int*   scat   = (const int*)d_in[4];     // [27, 60000]
    float* out = (float*)d_out;                    // [960000, 64]

    init_grid_kernel<<<(CELLS / 2 + 255) / 256, 256>>>();
    fill_grid_kernel<<<(NPTS + 255) / 256, 256>>>(scat, (const float2*)feat);
    center_weights_kernel<<<1, 256>>>(weight);
    fused_kernel<<<ROWS_TOTAL, 256>>>(gamma, beta, out);
}

// round 17
// speedup vs baseline: 1.9366x; 1.0653x over previous
#include <cuda_runtime.h>
#include <cstdint>
#include <math_constants.h>

#define NPTS   60000
#define KOFF   27
#define CIN    2
#define COUT   64
#define BB     2
#define DD     12
#define HH     200
#define WW     200
#define CELLS  960000        // 2*12*200*200
#define EPS_LN 1e-5f

#define ROWS_TOTAL (BB * DD * HH)        // 4800 blocks
#define WARPS_PER_BLOCK 8
#define CELLS_PER_WARP  (WW / WARPS_PER_BLOCK)   // 25
#define CHUNK 5                                   // cells processed per phase

#define GROW 202                                  // padded row: [-1 | 200 | -1]

#define SQ_SCALE   1048576.0f            // 2^20 fixed-point scale
#define SQ_UNSCALE 1.4901161e-8f         // 2^-20 / 64  (folds 1/COUT)

// Dense cell -> feature grid (7.7 MB, L2-resident). x = NaN marks empty.
__device__ float2 g_featgrid[CELLS];
// Centered weights: wc[j,cin,q] = w[j,cin,q] - (1/64) sum_q' w[j,cin,q'].
__device__ float g_wc[KOFF * CIN * COUT];

// Integer warp sum, single instruction (sm_80+).
__device__ __forceinline__ int warp_sum_i32(int v) {
    int r;
    asm volatile("redux.sync.add.s32 %0, %1, 0xffffffff;" : "=r"(r) : "r"(v));
    return r;
}

// --------------------------------------------------------------------------
// Kernel 1: init feature grid to (NaN, NaN).
// --------------------------------------------------------------------------
__global__ void init_grid_kernel() {
    const float nanf_ = CUDART_NAN_F;
    int i = blockIdx.x * blockDim.x + threadIdx.x;
    if (i < CELLS / 2)
        reinterpret_cast<float4*>(g_featgrid)[i] =
            make_float4(nanf_, nanf_, nanf_, nanf_);
}

// --------------------------------------------------------------------------
// Kernel 2: fill feature grid. scat[13*NPTS + n] is point n's own cell.
// --------------------------------------------------------------------------
__global__ void fill_grid_kernel(const int* __restrict__ scat,
                                 const float2* __restrict__ feat) {
    int n = blockIdx.x * blockDim.x + threadIdx.x;
    if (n < NPTS)
        g_featgrid[scat[13 * NPTS + n]] = feat[n];
}

// --------------------------------------------------------------------------
// Kernel 2b: precompute centered weights (one block, trivial).
// --------------------------------------------------------------------------
__global__ void center_weights_kernel(const float* __restrict__ weight) { // [27,2,64]
    __shared__ float sbar[KOFF * CIN];
    const int t = threadIdx.x;
    if (t < KOFF * CIN) {
        float s = 0.f;
        #pragma unroll 8
        for (int q = 0; q < COUT; q++)
            s += weight[t * COUT + q];
        sbar[t] = s * (1.f / COUT);
    }
    __syncthreads();
    for (int i = t; i < KOFF * CIN * COUT; i += blockDim.x)
        g_wc[i] = weight[i] - sbar[i / COUT];
}

// --------------------------------------------------------------------------
// Kernel 3: fused gather-conv + LayerNorm + ReLU.
// One block per (b, z, y) row; 9 neighbor FEATURE rows staged in smem with
// halo (NaN = empty) -> probe IS the gather. Warp per cell (5-cell chunks);
// lane i owns channels {2i, 2i+1}. Centered weights make accumulators
// mean-free. Var reduction via fixed-point REDUX.sync.add.s32 (no SHFLs).
// --------------------------------------------------------------------------
__global__ __launch_bounds__(256, 6) void fused_kernel(
        const float*  __restrict__ gamma,
        const float*  __restrict__ beta,
        float* __restrict__ out) {           // [CELLS, 64]
    __shared__ float4 swpx[KOFF][32];                         // 13824 B
    __shared__ float2 sfg[9 * GROW];                          // 14544 B
    __shared__ float2 sfeat[WARPS_PER_BLOCK][CHUNK][28];      //  8960 B

    // decode row
    const int row = blockIdx.x;          // (b*DD + z)*HH + y
    const int y   = row % HH;
    const int bz  = row / HH;            // b*DD + z
    const int z   = bz % DD;
    const int rowbase = row * WW;        // linear cell index of x=0

    // ---- stage centered weights: swpx[j][ln] = (w0.x, w0.y, w1.x, w1.y) ----
    const float2* wc2 = reinterpret_cast<const float2*>(g_wc);
    for (int i = threadIdx.x; i < KOFF * 32; i += blockDim.x) {
        const int j = i >> 5, ln = i & 31;
        const float2 w0 = wc2[(j * 2 + 0) * (COUT / 2) + ln];
        const float2 w1 = wc2[(j * 2 + 1) * (COUT / 2) + ln];
        swpx[j][ln] = make_float4(w0.x, w0.y, w1.x, w1.y);
    }

    // ---- stage 9 neighbor FEATURE rows with halo (NaN = empty/OOB) ----
    for (int i = threadIdx.x; i < 9 * GROW; i += blockDim.x) {
        const int r  = i / GROW;         // 0..8 -> (dz+1)*3 + (dy+1)
        const int c  = i - r * GROW;     // 0..201 -> x = c-1
        const int dz = r / 3 - 1;
        const int dy = r % 3 - 1;
        const int nz = z + dz, ny = y + dy, nx = c - 1;
        float2 v = make_float2(CUDART_NAN_F, CUDART_NAN_F);
        if ((unsigned)nz < DD && (unsigned)ny < HH && (unsigned)nx < WW)
            v = g_featgrid[rowbase + (dz * HH + dy) * WW + nx];
        sfg[i] = v;
    }
    __syncthreads();

    const int lane = threadIdx.x & 31;
    const int wib  = threadIdx.x >> 5;

    const float2 gg = reinterpret_cast<const float2*>(gamma)[lane];
    const float2 bb = reinterpret_cast<const float2*>(beta)[lane];

    // lane -> (k, smem probe base)
    const int dxl   = lane % 3;                         // dx+1 for lanes<27
    const int srow  = (lane < KOFF) ? (lane / 3) : 0;   // (dz+1)*3+(dy+1)
    const int pbase = srow * GROW + dxl;                // + x gives probe index
    const bool probing = (lane < KOFF);

    const int x0 = wib * CELLS_PER_WARP;

    for (int c0 = 0; c0 < CELLS_PER_WARP; c0 += CHUNK) {
        // ---- phase 1: probes return features directly (LDS.64) ----
        float2 f[CHUNK];
        #pragma unroll
        for (int ci = 0; ci < CHUNK; ci++) {
            const int x = x0 + c0 + ci;
            f[ci] = probing ? sfg[pbase + x]
                            : make_float2(CUDART_NAN_F, CUDART_NAN_F);
        }

        // ---- phase 2: ballots + in-register bounce to compact smem ----
        unsigned act[CHUNK];
        #pragma unroll
        for (int ci = 0; ci < CHUNK; ci++)
            act[ci] = __ballot_sync(0xffffffffu, f[ci].x == f[ci].x);
        #pragma unroll
        for (int ci = 0; ci < CHUNK; ci++)
            if (f[ci].x == f[ci].x)
                sfeat[wib][ci][lane] = f[ci];
        __syncwarp();

        // ---- phase 3: accumulate centered channels ----
        float A0[CHUNK], A1[CHUNK];
        int   SQI[CHUNK];
        #pragma unroll
        for (int ci = 0; ci < CHUNK; ci++) {
            float a0 = 0.f, a1 = 0.f;
            unsigned hits = act[ci];
            while (hits) {
                const int j = __ffs(hits) - 1;
                hits &= hits - 1;
                const float2 fj = sfeat[wib][ci][j];
                const float4 wp = swpx[j][lane];
                a0 = fmaf(fj.x, wp.x, fmaf(fj.y, wp.z, a0));
                a1 = fmaf(fj.x, wp.y, fmaf(fj.y, wp.w, a1));
            }
            A0[ci] = a0; A1[ci] = a1;
            const float sq = fmaf(a0, a0, a1 * a1);
            SQI[ci] = __float2int_rn(sq * SQ_SCALE);
        }

        // ---- phase 4: warp sums via single-instruction integer REDUX ----
        #pragma unroll
        for (int ci = 0; ci < CHUNK; ci++)
            SQI[ci] = warp_sum_i32(SQI[ci]);

        // ---- phase 5: normalize + relu + streaming store (imm offsets) ----
        float2* chunkout = reinterpret_cast<float2*>(
                               out + (size_t)(rowbase + x0 + c0) * COUT) + lane;
        #pragma unroll
        for (int ci = 0; ci < CHUNK; ci++) {
            const float sqf = (float)SQI[ci];
            const float inv = rsqrtf(fmaf(sqf, SQ_UNSCALE, EPS_LN));
            float r0 = fmaxf(fmaf(A0[ci] * inv, gg.x, bb.x), 0.f);
            float r1 = fmaxf(fmaf(A1[ci] * inv, gg.y, bb.y), 0.f);
            if (act[ci] == 0u) { r0 = 0.f; r1 = 0.f; }
            __stcs(chunkout + ci * (COUT / 2), make_float2(r0, r1));
        }
    }
}

// --------------------------------------------------------------------------
extern "C" void kernel_launch(void* const* d_in, const int* in_sizes, int n_in,
                              void* d_out, int out_size) {
    const float* feat   = (const float*)d_in[0];   // [60000, 2]
    const float* weight = (const float*)d_in[1];   // [27, 2, 64]
    const float* gamma  = (const float*)d_in[2];   // [64]
    const float* beta   = (const float*)d_in[3];   // [64]
    const int*   scat   = (const int*)d_in[4];     // [27, 60000]
    float* out = (float*)d_out;                    // [960000, 64]

    init_grid_kernel<<<(CELLS / 2 + 255) / 256, 256>>>();
    fill_grid_kernel<<<(NPTS + 255) / 256, 256>>>(scat, (const float2*)feat);
    center_weights_kernel<<<1, 256>>>(weight);
    fused_kernel<<<ROWS_TOTAL, 256>>>(gamma, beta, out);
}